// round 4
// baseline (speedup 1.0000x reference)
#include <cuda_runtime.h>

// HopfOscillatorModule, round 4: lane = oscillator, TWO adjacent rows in
// flight per warp, f32x2 FMAs packed over j (even/odd neighbors).
// Shared exchange fused: one float4 per j-pair = (x_even, x_odd, y_even, y_odd)
// -> 16 broadcast LDS.128 per row (was 32 LDS.64). Coefficient pairs
// (A_{i,2k},A_{i,2k+1}) live in 64-bit register pairs, loaded once.

#define NOSC 32
#define TWO_PI 6.283185307179586f
#define CTA_THREADS 128
#define WARPS_PER_CTA (CTA_THREADS / 32)
#define NUM_CTAS 1184   // 8 * 148 SMs

typedef unsigned long long u64;

__device__ float g_A[NOSC * NOSC];   // w*cos(phi), zero-diag, row-major [i][j]
__device__ float g_B[NOSC * NOSC];   // w*sin(phi), zero-diag
__device__ float4 g_par[NOSC];       // (K0, K1, K2, two_pi_v)

__device__ __forceinline__ float sigmoidf_(float x) { return 1.0f / (1.0f + expf(-x)); }

__global__ void hopf_setup_kernel(const float* __restrict__ v, const float* __restrict__ b,
                                  const float* __restrict__ c, const float* __restrict__ w,
                                  const float* __restrict__ phi)
{
    int k = threadIdx.x;  // flat index into 32x32 zero-diag matrices
    float A = 0.0f, Bc = 0.0f;
    if (k < 1023) {
        // _zero_diag: z = concat([zeros(31,1), P],1).ravel() ++ [0] -> (32,32)
        int t = k / 33, pos = k % 33;
        if (pos != 0) {
            float wa = sigmoidf_(w[t * 32 + pos - 1]);            // W_MAX = 1
            float pa = TWO_PI * sigmoidf_(phi[t * 32 + pos - 1]);
            float sp, cp;
            sincosf(pa, &sp, &cp);
            A = wa * cp;
            Bc = wa * sp;
        }
    }
    g_A[k] = A;
    g_B[k] = Bc;
    if (k < NOSC) {
        float va = 5.0f * sigmoidf_(v[k]);
        float ba = 2.0f * sigmoidf_(b[k]);
        float ca = 10.0f * sigmoidf_(c[k]);
        float K1 = 0.25f * ca * ca;
        g_par[k] = make_float4(K1 * ba, K1, ca, TWO_PI * va);  // r_d_dot = K0 - K1*r - K2*rd
    }
}

// ---------------- packed f32x2 helpers ----------------
__device__ __forceinline__ void ffma2(u64& d, u64 a, u64 b) {
    asm("fma.rn.f32x2 %0, %1, %2, %0;" : "+l"(d) : "l"(a), "l"(b));
}
__device__ __forceinline__ u64 sub2(u64 a, u64 b) {
    u64 r;
    asm("sub.rn.f32x2 %0, %1, %2;" : "=l"(r) : "l"(a), "l"(b));
    return r;
}
__device__ __forceinline__ u64 add2(u64 a, u64 b) {
    u64 r;
    asm("add.rn.f32x2 %0, %1, %2;" : "=l"(r) : "l"(a), "l"(b));
    return r;
}
__device__ __forceinline__ void upk2(u64 v, float& lo, float& hi) {
    asm("mov.b64 {%0, %1}, %2;" : "=f"(lo), "=f"(hi) : "l"(v));
}

__global__ __launch_bounds__(CTA_THREADS) void hopf_kernel(const float* __restrict__ in,
                                                           float* __restrict__ out,
                                                           int nrows, int stride_pairs)
{
    // Per j-pair slot: (x_{2jp}, x_{2jp+1}, y_{2jp}, y_{2jp+1}).
    // [double buffer][warp][row-in-pair][jp]
    __shared__ __align__(16) float4 sXY[2][WARPS_PER_CTA][2][NOSC / 2];

    int tid = threadIdx.x;
    int lane = tid & 31;
    int wid = tid >> 5;
    int jp_self = lane >> 1;
    int slot = lane & 1;

    // Per-lane coefficient row as 16 packed (even,odd) 64-bit pairs each.
    u64 PA[16], PB[16];
    {
        const u64* ga = (const u64*)(g_A + lane * NOSC);
        const u64* gb = (const u64*)(g_B + lane * NOSC);
#pragma unroll
        for (int jp = 0; jp < 16; jp++) {
            PA[jp] = ga[jp];
            PB[jp] = gb[jp];
        }
    }
    float4 par = g_par[lane];  // (K0, K1, K2, two_pi_v)

    int npairs = (nrows + 1) >> 1;
    int p = blockIdx.x * WARPS_PER_CTA + wid;
    int pb = 0;

    // Current pair state
    float psiA = 0.f, rrA = 0.f, rdA = 0.f;
    float psiB = 0.f, rrB = 0.f, rdB = 0.f;
    bool hasB = false;
    if (p < npairs) {
        int row0 = 2 * p;
        const float* rp = in + (size_t)row0 * 96;
        psiA = rp[lane];
        rrA = rp[32 + lane];
        rdA = rp[64 + lane];
        hasB = (row0 + 1) < nrows;
        const float* rq = rp + (hasB ? 96 : 0);
        psiB = rq[lane];
        rrB = rq[32 + lane];
        rdB = rq[64 + lane];
    }

    while (p < npairs) {
        int pn = p + stride_pairs;

        float sA, cA, sB, cB;
        __sincosf(psiA, &sA, &cA);
        __sincosf(psiB, &sB, &cB);

        // Scatter x/y into the fused float4 slots (2-way bank conflict, cheap).
        float* slA = (float*)&sXY[pb][wid][0][jp_self];
        float* slB = (float*)&sXY[pb][wid][1][jp_self];
        slA[slot] = rrA * sA;
        slA[2 + slot] = rrA * cA;
        slB[slot] = rrB * sB;
        slB[2 + slot] = rrB * cB;

        // Prefetch next pair while the j-loop runs.
        float npsiA = 0.f, nrrA = 0.f, nrdA = 0.f;
        float npsiB = 0.f, nrrB = 0.f, nrdB = 0.f;
        bool nhasB = false;
        if (pn < npairs) {
            int row0 = 2 * pn;
            const float* rp = in + (size_t)row0 * 96;
            npsiA = rp[lane];
            nrrA = rp[32 + lane];
            nrdA = rp[64 + lane];
            nhasB = (row0 + 1) < nrows;
            const float* rq = rp + (nhasB ? 96 : 0);
            npsiB = rq[lane];
            nrrB = rq[32 + lane];
            nrdB = rq[64 + lane];
        }
        __syncwarp();

        const ulonglong2* bA = (const ulonglong2*)sXY[pb][wid][0];
        const ulonglong2* bB = (const ulonglong2*)sXY[pb][wid][1];
        u64 P1a = 0ull, P2a = 0ull, Q1a = 0ull, Q2a = 0ull;
        u64 P1b = 0ull, P2b = 0ull, Q1b = 0ull, Q2b = 0ull;
#pragma unroll
        for (int jp = 0; jp < 16; jp++) {
            ulonglong2 va = bA[jp];   // LDS.128 broadcast: (x-pair, y-pair) row A
            ulonglong2 vb = bB[jp];   // row B
            u64 a2 = PA[jp], b2 = PB[jp];
            ffma2(P1a, a2, va.x);
            ffma2(P2a, b2, va.y);
            ffma2(Q1a, b2, va.x);
            ffma2(Q2a, a2, va.y);
            ffma2(P1b, a2, vb.x);
            ffma2(P2b, b2, vb.y);
            ffma2(Q1b, b2, vb.x);
            ffma2(Q2b, a2, vb.y);
        }

        u64 Pa = sub2(P1a, P2a), Qa = add2(Q1a, Q2a);
        u64 Pb = sub2(P1b, P2b), Qb = add2(Q1b, Q2b);
        float pl, ph, ql, qh;

        upk2(Pa, pl, ph);
        upk2(Qa, ql, qh);
        float psidotA = fmaf(cA, pl + ph, fmaf(-sA, ql + qh, par.w));
        float fA = fmaf(-par.z, rdA, fmaf(-par.y, rrA, par.x));

        upk2(Pb, pl, ph);
        upk2(Qb, ql, qh);
        float psidotB = fmaf(cB, pl + ph, fmaf(-sB, ql + qh, par.w));
        float fB = fmaf(-par.z, rdB, fmaf(-par.y, rrB, par.x));

        int row0 = 2 * p;
        float* o = out + (size_t)row0 * 96;
        o[lane] = psidotA;
        o[32 + lane] = rdA;
        o[64 + lane] = fA;
        if (hasB) {
            o[96 + lane] = psidotB;
            o[128 + lane] = rdB;
            o[160 + lane] = fB;
        }

        psiA = npsiA; rrA = nrrA; rdA = nrdA;
        psiB = npsiB; rrB = nrrB; rdB = nrdB;
        hasB = nhasB;
        p = pn;
        pb ^= 1;
    }
}

extern "C" void kernel_launch(void* const* d_in, const int* in_sizes, int n_in,
                              void* d_out, int out_size)
{
    const float* states = (const float*)d_in[0];
    const float* v = (const float*)d_in[1];
    const float* b = (const float*)d_in[2];
    const float* c = (const float*)d_in[3];
    const float* w = (const float*)d_in[4];
    const float* phi = (const float*)d_in[5];
    int nrows = in_sizes[0] / 96;

    hopf_setup_kernel<<<1, 1024>>>(v, b, c, w, phi);

    int stride_pairs = NUM_CTAS * WARPS_PER_CTA;
    hopf_kernel<<<NUM_CTAS, CTA_THREADS>>>(states, (float*)d_out, nrows, stride_pairs);
}

// round 6
// speedup vs baseline: 1.1452x; 1.1452x over previous
#include <cuda_runtime.h>
#include <cuda_bf16.h>
#include <cstdint>

// HopfOscillatorModule, round 6: coupling as an HMMA (mma.sync) bf16-split GEMM.
//   [P|Q](row) = [x|y](row) . M,  M 64x64 constant:
//     col n<32  (P_n): k<32 (x_j): A[n][j],  k>=32 (y_j): -B[n][j]
//     col n>=32 (Q_n): k<32:      B[n][j],  k>=32:       A[n][j]
//   psi_dot_i = 2*pi*v_i + cos(psi_i)*P_i - sin(psi_i)*Q_i
// 3-chunk bf16 split (AhiBhi + AloBhi + AhiBlo) into one f32 accumulator.
// No tcgen05 (ptxas target is plain sm_103) — classic mma.sync + ldmatrix.

#define NOSC 32
#define TILE_ROWS 128
#define TWO_PI 6.283185307179586f

typedef unsigned int u32;

// SMEM layout (dynamic). A rows padded to 144B for conflict-free ldmatrix.
#define A_STRIDE 144
#define B_STRIDE 144
#define OFF_AHI 0                      // 128*144 = 18432
#define OFF_ALO 18432                  // 18432 -> 36864
#define OFF_BHI 36864                  // 64*144 = 9216 -> 46080
#define OFF_BLO 46080                  // 9216 -> 55296
#define OFF_PAR 55296                  // 512 -> 55808
#define OFF_PQ  0                      // overlay after MMA: 128 * 66 floats = 33792
#define PQ_STRIDE 66                   // floats
#define SMEM_TOTAL 55808

__device__ __align__(16) unsigned char g_Bhi[64 * B_STRIDE];
__device__ __align__(16) unsigned char g_Blo[64 * B_STRIDE];
__device__ float4 g_par[NOSC];   // (K0, K1, K2, two_pi_v)

__device__ __forceinline__ float sigmoidf_(float x) { return 1.0f / (1.0f + expf(-x)); }

// ---------------- setup ----------------
__global__ void hopf_setup_kernel(const float* __restrict__ v, const float* __restrict__ b,
                                  const float* __restrict__ c, const float* __restrict__ w,
                                  const float* __restrict__ phi)
{
    int tid = threadIdx.x;
    if (tid < NOSC) {
        float va = 5.0f * sigmoidf_(v[tid]);
        float ba = 2.0f * sigmoidf_(b[tid]);
        float ca = 10.0f * sigmoidf_(c[tid]);
        float K1 = 0.25f * ca * ca;
        g_par[tid] = make_float4(K1 * ba, K1, ca, TWO_PI * va);
    }
    for (int e = tid; e < 64 * 64; e += blockDim.x) {
        int n = e >> 6, k = e & 63;
        int j = k & 31;
        bool is_x = (k < 32);
        int i = n & 31;
        int flat = 32 * i + j;                     // index into zero-diag 32x32
        float A = 0.0f, Bc = 0.0f;
        if (flat != 1023) {
            // _zero_diag: z = concat([zeros(31,1), P],1).ravel() ++ [0] -> (32,32)
            int t = flat / 33, pos = flat % 33;
            if (pos != 0) {
                float wa = sigmoidf_(w[t * 32 + pos - 1]);            // W_MAX = 1
                float pa = TWO_PI * sigmoidf_(phi[t * 32 + pos - 1]);
                float sp, cp;
                sincosf(pa, &sp, &cp);
                A = wa * cp;
                Bc = wa * sp;
            }
        }
        float Mf;
        if (n < 32) Mf = is_x ? A : -Bc;     // P part
        else        Mf = is_x ? Bc : A;      // Q part
        __nv_bfloat16 hi = __float2bfloat16_rn(Mf);
        __nv_bfloat16 lo = __float2bfloat16_rn(Mf - __bfloat162float(hi));
        *(__nv_bfloat16*)(g_Bhi + n * B_STRIDE + k * 2) = hi;
        *(__nv_bfloat16*)(g_Blo + n * B_STRIDE + k * 2) = lo;
    }
}

// ---------------- ptx helpers ----------------
__device__ __forceinline__ u32 smem_u32(const void* p) {
    u32 a;
    asm("{ .reg .u64 t; cvta.to.shared.u64 t, %1; cvt.u32.u64 %0, t; }" : "=r"(a) : "l"(p));
    return a;
}
__device__ __forceinline__ void ldm4(u32* r, u32 addr) {
    asm volatile("ldmatrix.sync.aligned.m8n8.x4.shared.b16 {%0,%1,%2,%3}, [%4];"
                 : "=r"(r[0]), "=r"(r[1]), "=r"(r[2]), "=r"(r[3]) : "r"(addr));
}
__device__ __forceinline__ void mma16816(float* d, const u32* a, const u32 b0, const u32 b1) {
    asm volatile(
        "mma.sync.aligned.m16n8k16.row.col.f32.bf16.bf16.f32 "
        "{%0,%1,%2,%3}, {%4,%5,%6,%7}, {%8,%9}, {%0,%1,%2,%3};"
        : "+f"(d[0]), "+f"(d[1]), "+f"(d[2]), "+f"(d[3])
        : "r"(a[0]), "r"(a[1]), "r"(a[2]), "r"(a[3]), "r"(b0), "r"(b1));
}

// ---------------- main kernel ----------------
__global__ __launch_bounds__(128)
void hopf_kernel(const float* __restrict__ in, float* __restrict__ out, int nrows)
{
    extern __shared__ __align__(16) char smem[];
    u32 sb = smem_u32(smem);
    int tid = threadIdx.x;
    int lane = tid & 31;
    int wid = tid >> 5;

    // Copy constant B tiles + params into SMEM.
    {
        const uint4* gh = (const uint4*)g_Bhi;
        const uint4* gl = (const uint4*)g_Blo;
        uint4* sh = (uint4*)(smem + OFF_BHI);
        uint4* sl = (uint4*)(smem + OFF_BLO);
        for (int i = tid; i < (64 * B_STRIDE) / 16; i += 128) {
            sh[i] = gh[i];
            sl[i] = gl[i];
        }
        if (tid < NOSC) ((float4*)(smem + OFF_PAR))[tid] = g_par[tid];
    }

    // Prologue: build A tiles. Row layout: [x0..x31 | y0..y31] bf16 (128B + pad).
    int base = blockIdx.x * TILE_ROWS;
#pragma unroll
    for (int it = 0; it < 8; it++) {
        int idx = tid + 128 * it;          // 0..1023
        int r = idx >> 3, q = idx & 7;     // row-in-tile, j-quad
        int row = base + r;
        float4 p4 = make_float4(0.f, 0.f, 0.f, 0.f);
        float4 r4 = make_float4(0.f, 0.f, 0.f, 0.f);
        if (row < nrows) {
            const float4* rp = (const float4*)(in + (size_t)row * 96);
            p4 = rp[q];
            r4 = rp[8 + q];
        }
        float px[4] = {p4.x, p4.y, p4.z, p4.w};
        float rx[4] = {r4.x, r4.y, r4.z, r4.w};
        float X[4], Y[4];
#pragma unroll
        for (int e = 0; e < 4; e++) {
            float s, c;
            __sincosf(px[e], &s, &c);
            X[e] = rx[e] * s;
            Y[e] = rx[e] * c;
        }
        __nv_bfloat162 xh01 = __floats2bfloat162_rn(X[0], X[1]);
        __nv_bfloat162 xh23 = __floats2bfloat162_rn(X[2], X[3]);
        __nv_bfloat162 yh01 = __floats2bfloat162_rn(Y[0], Y[1]);
        __nv_bfloat162 yh23 = __floats2bfloat162_rn(Y[2], Y[3]);
        __nv_bfloat162 xl01 = __floats2bfloat162_rn(X[0] - __bfloat162float(xh01.x),
                                                    X[1] - __bfloat162float(xh01.y));
        __nv_bfloat162 xl23 = __floats2bfloat162_rn(X[2] - __bfloat162float(xh23.x),
                                                    X[3] - __bfloat162float(xh23.y));
        __nv_bfloat162 yl01 = __floats2bfloat162_rn(Y[0] - __bfloat162float(yh01.x),
                                                    Y[1] - __bfloat162float(yh01.y));
        __nv_bfloat162 yl23 = __floats2bfloat162_rn(Y[2] - __bfloat162float(yh23.x),
                                                    Y[3] - __bfloat162float(yh23.y));
        u32 xo = r * A_STRIDE + q * 8;       // x quad (4 bf16 = 8B)
        u32 yo = xo + 64;                    // y quad
        *(uint2*)(smem + OFF_AHI + xo) = make_uint2(*(u32*)&xh01, *(u32*)&xh23);
        *(uint2*)(smem + OFF_AHI + yo) = make_uint2(*(u32*)&yh01, *(u32*)&yh23);
        *(uint2*)(smem + OFF_ALO + xo) = make_uint2(*(u32*)&xl01, *(u32*)&xl23);
        *(uint2*)(smem + OFF_ALO + yo) = make_uint2(*(u32*)&yl01, *(u32*)&yl23);
    }
    __syncthreads();

    // ---------------- MMA phase: warp owns 32 rows x 64 cols ----------------
    int mrow = wid * 32;
    float acc[2][8][4];
#pragma unroll
    for (int ms = 0; ms < 2; ms++)
#pragma unroll
        for (int nt = 0; nt < 8; nt++)
#pragma unroll
            for (int e = 0; e < 4; e++) acc[ms][nt][e] = 0.0f;

    int lrow = lane & 15;            // ldmatrix row provider within 16
    int lhalf = lane >> 4;           // 0: k 0-7 cols, 1: k 8-15 (x4 quadrants 2,3)

#pragma unroll
    for (int chunk = 0; chunk < 3; chunk++) {
        u32 Aoff = sb + ((chunk == 1) ? OFF_ALO : OFF_AHI);
        u32 Boff = sb + ((chunk == 2) ? OFF_BLO : OFF_BHI);
#pragma unroll
        for (int ks = 0; ks < 4; ks++) {
            u32 kb = ks * 32 + lhalf * 16;   // byte offset of this lane's k-chunk
            u32 a[2][4];
#pragma unroll
            for (int ms = 0; ms < 2; ms++) {
                u32 addr = Aoff + (u32)((mrow + ms * 16 + lrow) * A_STRIDE) + kb;
                ldm4(a[ms], addr);
            }
            u32 bfr[4][4];
#pragma unroll
            for (int nb = 0; nb < 4; nb++) {
                u32 addr = Boff + (u32)((nb * 16 + lrow) * B_STRIDE) + kb;
                ldm4(bfr[nb], addr);
            }
#pragma unroll
            for (int ms = 0; ms < 2; ms++)
#pragma unroll
                for (int nb = 0; nb < 4; nb++) {
                    mma16816(acc[ms][2 * nb + 0], a[ms], bfr[nb][0], bfr[nb][2]);
                    mma16816(acc[ms][2 * nb + 1], a[ms], bfr[nb][1], bfr[nb][3]);
                }
        }
    }

    // PQ staging overlays the A region — must not clobber before all warps done.
    __syncthreads();

    float* sPQ = (float*)(smem + OFF_PQ);
    int g = lane >> 2;           // fragment row group
    int tc = (lane & 3) * 2;     // fragment col pair
#pragma unroll
    for (int ms = 0; ms < 2; ms++) {
        int r0 = mrow + ms * 16 + g;
#pragma unroll
        for (int nt = 0; nt < 8; nt++) {
            int col = nt * 8 + tc;
            *(float2*)(sPQ + r0 * PQ_STRIDE + col) =
                make_float2(acc[ms][nt][0], acc[ms][nt][1]);
            *(float2*)(sPQ + (r0 + 8) * PQ_STRIDE + col) =
                make_float2(acc[ms][nt][2], acc[ms][nt][3]);
        }
    }
    __syncthreads();

    // ---------------- epilogue: coalesced, lane = oscillator ----------------
    float4 par = ((const float4*)(smem + OFF_PAR))[lane];
#pragma unroll 4
    for (int rr = 0; rr < 32; rr++) {
        int rt = wid * 32 + rr;
        int row = base + rt;
        if (row < nrows) {
            float Pv = sPQ[rt * PQ_STRIDE + lane];
            float Qv = sPQ[rt * PQ_STRIDE + 32 + lane];
            const float* ip = in + (size_t)row * 96;
            float psi = ip[lane], rv = ip[32 + lane], rdv = ip[64 + lane];
            float s, c;
            __sincosf(psi, &s, &c);
            float psidot = fmaf(c, Pv, fmaf(-s, Qv, par.w));
            float f = fmaf(-par.z, rdv, fmaf(-par.y, rv, par.x));
            float* op = out + (size_t)row * 96;
            op[lane] = psidot;
            op[32 + lane] = rdv;
            op[64 + lane] = f;
        }
    }
}

extern "C" void kernel_launch(void* const* d_in, const int* in_sizes, int n_in,
                              void* d_out, int out_size)
{
    const float* states = (const float*)d_in[0];
    const float* v = (const float*)d_in[1];
    const float* b = (const float*)d_in[2];
    const float* c = (const float*)d_in[3];
    const float* w = (const float*)d_in[4];
    const float* phi = (const float*)d_in[5];
    int nrows = in_sizes[0] / 96;

    cudaFuncSetAttribute(hopf_kernel, cudaFuncAttributeMaxDynamicSharedMemorySize,
                         SMEM_TOTAL);

    hopf_setup_kernel<<<1, 1024>>>(v, b, c, w, phi);

    int grid = (nrows + TILE_ROWS - 1) / TILE_ROWS;
    hopf_kernel<<<grid, 128, SMEM_TOTAL>>>(states, (float*)d_out, nrows);
}

// round 7
// speedup vs baseline: 1.6342x; 1.4270x over previous
#include <cuda_runtime.h>
#include <cuda_bf16.h>
#include <cstdint>

// HopfOscillatorModule, round 7: HMMA bf16-split GEMM, 256-thread CTAs.
//   [P|Q](row) = [x|y](row) . M,  M 64x64 constant.
//   psi_dot_i = 2*pi*v_i + cos(psi_i)*P_i - sin(psi_i)*Q_i
// 3-chunk bf16 split (AhiBhi + AloBhi + AhiBlo), f32 accum.
// r_d / r_d_dot written straight from the prologue; (cos,sin) cached in SMEM
// so the epilogue is pure LDS+FMA+STG. 2 CTAs/SM for phase overlap.

#define NOSC 32
#define TILE_ROWS 128
#define TWO_PI 6.283185307179586f

typedef unsigned int u32;

#define A_STRIDE 144
#define B_STRIDE 144
#define OFF_AHI 0                      // 128*144 = 18432
#define OFF_ALO 18432                  // -> 36864
#define OFF_BHI 36864                  // 64*144 = 9216 -> 46080
#define OFF_BLO 46080                  // -> 55296
#define OFF_CS  55296                  // float2[128][32] = 32768 -> 88064
#define OFF_TPV 88064                  // float[32] = 128 -> 88192
#define OFF_PQ  0                      // overlay after MMA: 128*66 floats = 33792
#define PQ_STRIDE 66
#define SMEM_TOTAL 88192

__device__ __align__(16) unsigned char g_Bhi[64 * B_STRIDE];
__device__ __align__(16) unsigned char g_Blo[64 * B_STRIDE];
__device__ __align__(16) float g_K0[NOSC];
__device__ __align__(16) float g_K1[NOSC];
__device__ __align__(16) float g_K2[NOSC];
__device__ __align__(16) float g_tpv[NOSC];

__device__ __forceinline__ float sigmoidf_(float x) { return 1.0f / (1.0f + expf(-x)); }

// ---------------- setup ----------------
__global__ void hopf_setup_kernel(const float* __restrict__ v, const float* __restrict__ b,
                                  const float* __restrict__ c, const float* __restrict__ w,
                                  const float* __restrict__ phi)
{
    int tid = threadIdx.x;
    if (tid < NOSC) {
        float va = 5.0f * sigmoidf_(v[tid]);
        float ba = 2.0f * sigmoidf_(b[tid]);
        float ca = 10.0f * sigmoidf_(c[tid]);
        float K1 = 0.25f * ca * ca;
        g_K0[tid] = K1 * ba;
        g_K1[tid] = K1;
        g_K2[tid] = ca;
        g_tpv[tid] = TWO_PI * va;
    }
    for (int e = tid; e < 64 * 64; e += blockDim.x) {
        int n = e >> 6, k = e & 63;
        int j = k & 31;
        bool is_x = (k < 32);
        int i = n & 31;
        int flat = 32 * i + j;                     // index into zero-diag 32x32
        float A = 0.0f, Bc = 0.0f;
        if (flat != 1023) {
            // _zero_diag: z = concat([zeros(31,1), P],1).ravel() ++ [0] -> (32,32)
            int t = flat / 33, pos = flat % 33;
            if (pos != 0) {
                float wa = sigmoidf_(w[t * 32 + pos - 1]);            // W_MAX = 1
                float pa = TWO_PI * sigmoidf_(phi[t * 32 + pos - 1]);
                float sp, cp;
                sincosf(pa, &sp, &cp);
                A = wa * cp;
                Bc = wa * sp;
            }
        }
        float Mf;
        if (n < 32) Mf = is_x ? A : -Bc;     // P part
        else        Mf = is_x ? Bc : A;      // Q part
        __nv_bfloat16 hi = __float2bfloat16_rn(Mf);
        __nv_bfloat16 lo = __float2bfloat16_rn(Mf - __bfloat162float(hi));
        *(__nv_bfloat16*)(g_Bhi + n * B_STRIDE + k * 2) = hi;
        *(__nv_bfloat16*)(g_Blo + n * B_STRIDE + k * 2) = lo;
    }
}

// ---------------- ptx helpers ----------------
__device__ __forceinline__ u32 smem_u32(const void* p) {
    u32 a;
    asm("{ .reg .u64 t; cvta.to.shared.u64 t, %1; cvt.u32.u64 %0, t; }" : "=r"(a) : "l"(p));
    return a;
}
__device__ __forceinline__ void ldm4(u32* r, u32 addr) {
    asm volatile("ldmatrix.sync.aligned.m8n8.x4.shared.b16 {%0,%1,%2,%3}, [%4];"
                 : "=r"(r[0]), "=r"(r[1]), "=r"(r[2]), "=r"(r[3]) : "r"(addr));
}
__device__ __forceinline__ void mma16816(float* d, const u32* a, const u32 b0, const u32 b1) {
    asm volatile(
        "mma.sync.aligned.m16n8k16.row.col.f32.bf16.bf16.f32 "
        "{%0,%1,%2,%3}, {%4,%5,%6,%7}, {%8,%9}, {%0,%1,%2,%3};"
        : "+f"(d[0]), "+f"(d[1]), "+f"(d[2]), "+f"(d[3])
        : "r"(a[0]), "r"(a[1]), "r"(a[2]), "r"(a[3]), "r"(b0), "r"(b1));
}

// ---------------- main kernel ----------------
__global__ __launch_bounds__(256, 2)
void hopf_kernel(const float* __restrict__ in, float* __restrict__ out, int nrows)
{
    extern __shared__ __align__(16) char smem[];
    u32 sb = smem_u32(smem);
    int tid = threadIdx.x;
    int lane = tid & 31;
    int wid = tid >> 5;

    // Stage constant B tiles + tpv.
    {
        const uint4* gh = (const uint4*)g_Bhi;
        const uint4* gl = (const uint4*)g_Blo;
        uint4* sh = (uint4*)(smem + OFF_BHI);
        uint4* sl = (uint4*)(smem + OFF_BLO);
        for (int i = tid; i < (64 * B_STRIDE) / 16; i += 256) {
            sh[i] = gh[i];
            sl[i] = gl[i];
        }
        if (tid < NOSC) ((float*)(smem + OFF_TPV))[tid] = g_tpv[tid];
    }

    int base = blockIdx.x * TILE_ROWS;
    {
        // Per-thread q (j-quad) is invariant across prologue iterations.
        int q = tid & 7;
        float4 K0 = ((const float4*)g_K0)[q];
        float4 K1 = ((const float4*)g_K1)[q];
        float4 K2 = ((const float4*)g_K2)[q];
        float k0a[4] = {K0.x, K0.y, K0.z, K0.w};
        float k1a[4] = {K1.x, K1.y, K1.z, K1.w};
        float k2a[4] = {K2.x, K2.y, K2.z, K2.w};

#pragma unroll
        for (int it = 0; it < 4; it++) {
            int r = (tid >> 3) + 32 * it;      // row-in-tile
            int row = base + r;
            float4 p4 = make_float4(0.f, 0.f, 0.f, 0.f);
            float4 r4 = make_float4(0.f, 0.f, 0.f, 0.f);
            float4 d4 = make_float4(0.f, 0.f, 0.f, 0.f);
            if (row < nrows) {
                const float4* rp = (const float4*)(in + (size_t)row * 96);
                p4 = rp[q];
                r4 = rp[8 + q];
                d4 = rp[16 + q];
            }
            float px[4] = {p4.x, p4.y, p4.z, p4.w};
            float rx[4] = {r4.x, r4.y, r4.z, r4.w};
            float dx[4] = {d4.x, d4.y, d4.z, d4.w};
            float X[4], Y[4], S[4], C[4], F[4];
#pragma unroll
            for (int e = 0; e < 4; e++) {
                __sincosf(px[e], &S[e], &C[e]);
                X[e] = rx[e] * S[e];
                Y[e] = rx[e] * C[e];
                F[e] = fmaf(-k2a[e], dx[e], fmaf(-k1a[e], rx[e], k0a[e]));
            }
            // (cos,sin) cache for the epilogue.
            u32 cso = OFF_CS + (u32)(r * 256 + q * 32);
            *(float4*)(smem + cso) = make_float4(C[0], S[0], C[1], S[1]);
            *(float4*)(smem + cso + 16) = make_float4(C[2], S[2], C[3], S[3]);

            // bf16 hi/lo split of x|y into the A tiles.
            __nv_bfloat162 xh01 = __floats2bfloat162_rn(X[0], X[1]);
            __nv_bfloat162 xh23 = __floats2bfloat162_rn(X[2], X[3]);
            __nv_bfloat162 yh01 = __floats2bfloat162_rn(Y[0], Y[1]);
            __nv_bfloat162 yh23 = __floats2bfloat162_rn(Y[2], Y[3]);
            __nv_bfloat162 xl01 = __floats2bfloat162_rn(X[0] - __bfloat162float(xh01.x),
                                                        X[1] - __bfloat162float(xh01.y));
            __nv_bfloat162 xl23 = __floats2bfloat162_rn(X[2] - __bfloat162float(xh23.x),
                                                        X[3] - __bfloat162float(xh23.y));
            __nv_bfloat162 yl01 = __floats2bfloat162_rn(Y[0] - __bfloat162float(yh01.x),
                                                        Y[1] - __bfloat162float(yh01.y));
            __nv_bfloat162 yl23 = __floats2bfloat162_rn(Y[2] - __bfloat162float(yh23.x),
                                                        Y[3] - __bfloat162float(yh23.y));
            u32 xo = r * A_STRIDE + q * 8;
            u32 yo = xo + 64;
            *(uint2*)(smem + OFF_AHI + xo) = make_uint2(*(u32*)&xh01, *(u32*)&xh23);
            *(uint2*)(smem + OFF_AHI + yo) = make_uint2(*(u32*)&yh01, *(u32*)&yh23);
            *(uint2*)(smem + OFF_ALO + xo) = make_uint2(*(u32*)&xl01, *(u32*)&xl23);
            *(uint2*)(smem + OFF_ALO + yo) = make_uint2(*(u32*)&yl01, *(u32*)&yl23);

            // r_d and r_d_dot don't depend on the MMA — store now, coalesced.
            if (row < nrows) {
                float4* op = (float4*)(out + (size_t)row * 96);
                op[8 + q] = d4;
                op[16 + q] = make_float4(F[0], F[1], F[2], F[3]);
            }
        }
    }
    __syncthreads();

    // ---------------- MMA: warp owns 16 rows x 64 cols ----------------
    int mrow = wid * 16;
    float acc[8][4];
#pragma unroll
    for (int nt = 0; nt < 8; nt++)
#pragma unroll
        for (int e = 0; e < 4; e++) acc[nt][e] = 0.0f;

    int lrow = lane & 15;
    int lhalf = lane >> 4;

#pragma unroll
    for (int chunk = 0; chunk < 3; chunk++) {
        u32 Aoff = sb + ((chunk == 1) ? OFF_ALO : OFF_AHI);
        u32 Boff = sb + ((chunk == 2) ? OFF_BLO : OFF_BHI);
#pragma unroll
        for (int ks = 0; ks < 4; ks++) {
            u32 kb = ks * 32 + lhalf * 16;
            u32 a[4];
            ldm4(a, Aoff + (u32)((mrow + lrow) * A_STRIDE) + kb);
            u32 bfr[4][4];
#pragma unroll
            for (int nb = 0; nb < 4; nb++)
                ldm4(bfr[nb], Boff + (u32)((nb * 16 + lrow) * B_STRIDE) + kb);
#pragma unroll
            for (int nb = 0; nb < 4; nb++) {
                mma16816(acc[2 * nb + 0], a, bfr[nb][0], bfr[nb][2]);
                mma16816(acc[2 * nb + 1], a, bfr[nb][1], bfr[nb][3]);
            }
        }
    }

    __syncthreads();   // all A reads done before PQ overlays the A region

    float* sPQ = (float*)(smem + OFF_PQ);
    {
        int g = lane >> 2;
        int tc = (lane & 3) * 2;
        int r0 = mrow + g;
#pragma unroll
        for (int nt = 0; nt < 8; nt++) {
            int col = nt * 8 + tc;
            *(float2*)(sPQ + r0 * PQ_STRIDE + col) = make_float2(acc[nt][0], acc[nt][1]);
            *(float2*)(sPQ + (r0 + 8) * PQ_STRIDE + col) = make_float2(acc[nt][2], acc[nt][3]);
        }
    }
    __syncthreads();

    // ---------------- epilogue: pure LDS + FMA + STG ----------------
    float tpv = ((const float*)(smem + OFF_TPV))[lane];
    const float2* sCS = (const float2*)(smem + OFF_CS);
#pragma unroll 4
    for (int rr = 0; rr < 16; rr++) {
        int rt = wid * 16 + rr;
        int row = base + rt;
        if (row < nrows) {
            float Pv = sPQ[rt * PQ_STRIDE + lane];
            float Qv = sPQ[rt * PQ_STRIDE + 32 + lane];
            float2 cs = sCS[rt * 32 + lane];       // (cos, sin)
            float psidot = fmaf(cs.x, Pv, fmaf(-cs.y, Qv, tpv));
            out[(size_t)row * 96 + lane] = psidot;
        }
    }
}

extern "C" void kernel_launch(void* const* d_in, const int* in_sizes, int n_in,
                              void* d_out, int out_size)
{
    const float* states = (const float*)d_in[0];
    const float* v = (const float*)d_in[1];
    const float* b = (const float*)d_in[2];
    const float* c = (const float*)d_in[3];
    const float* w = (const float*)d_in[4];
    const float* phi = (const float*)d_in[5];
    int nrows = in_sizes[0] / 96;

    cudaFuncSetAttribute(hopf_kernel, cudaFuncAttributeMaxDynamicSharedMemorySize,
                         SMEM_TOTAL);

    hopf_setup_kernel<<<1, 1024>>>(v, b, c, w, phi);

    int grid = (nrows + TILE_ROWS - 1) / TILE_ROWS;
    hopf_kernel<<<grid, 256, SMEM_TOTAL>>>(states, (float*)d_out, nrows);
}